// round 1
// baseline (speedup 1.0000x reference)
#include <cuda_runtime.h>
#include <math.h>

// Shapes are fixed by the problem: N=8192, K=512 (Fin), F=256 (Fout).
#define N_ROWS 8192
#define K_DIM  512
#define F_DIM  256
#define NCHUNK 128          // scan chunks
#define CHUNK  64           // rows per chunk (128*64 = 8192)

// ---------------- scratch (device globals; no allocation allowed) ----------------
__device__ float g_h[N_ROWS * F_DIM];            // h = x @ W
__device__ float g_f[N_ROWS];
__device__ float g_g[N_ROWS];
__device__ float g_gs[N_ROWS];                   // g sorted ascending
__device__ int   g_gidx[N_ROWS];                 // argsort
__device__ float g_scal[4];                      // [0] = gmax
__device__ float g_pH[NCHUNK * F_DIM];           // per-chunk sums of h
__device__ float g_pE[NCHUNK * F_DIM];           // per-chunk sums of w*h
__device__ float g_pW[NCHUNK];                   // per-chunk sums of w
__device__ float g_chOffH[NCHUNK * F_DIM];       // exclusive prefix of chunk sums
__device__ float g_chOffE[NCHUNK * F_DIM];       // exclusive suffix of chunk sums
__device__ float g_chOffW[NCHUNK];
__device__ float g_prefH[(N_ROWS + 1) * F_DIM];  // prefH[k] = sum_{m<k} h[sorted m]
__device__ float g_sufE[(N_ROWS + 1) * F_DIM];   // sufE[k]  = sum_{m>=k} w_m h[sorted m]
__device__ float g_sufW[N_ROWS + 1];             // scalar suffix of w

// ---------------- 1) GEMM: h = x @ W   (128x128 tile, 8x8 microtile) ----------------
__global__ void gemm_h_kernel(const float* __restrict__ x, const float* __restrict__ W) {
    __shared__ float As[16][128];   // [k][m]
    __shared__ float Bs[16][128];   // [k][n]
    const int bm = blockIdx.y * 128;
    const int bn = blockIdx.x * 128;
    const int tid = threadIdx.x;
    const int tx = tid & 15;        // 0..15 -> 8 cols each
    const int ty = tid >> 4;        // 0..15 -> 8 rows each

    float acc[8][8];
    #pragma unroll
    for (int i = 0; i < 8; i++)
        #pragma unroll
        for (int j = 0; j < 8; j++) acc[i][j] = 0.f;

    for (int k0 = 0; k0 < K_DIM; k0 += 16) {
        // load A tile 128x16 (512 float4)
        #pragma unroll
        for (int l = 0; l < 2; l++) {
            int idx = tid + l * 256;
            int r = idx >> 2;
            int c4 = (idx & 3) << 2;
            float4 v = *(const float4*)(x + (size_t)(bm + r) * K_DIM + k0 + c4);
            As[c4 + 0][r] = v.x; As[c4 + 1][r] = v.y;
            As[c4 + 2][r] = v.z; As[c4 + 3][r] = v.w;
        }
        // load B tile 16x128 (512 float4)
        #pragma unroll
        for (int l = 0; l < 2; l++) {
            int idx = tid + l * 256;
            int r = idx >> 5;
            int c4 = (idx & 31) << 2;
            *(float4*)&Bs[r][c4] = *(const float4*)(W + (size_t)(k0 + r) * F_DIM + bn + c4);
        }
        __syncthreads();
        #pragma unroll
        for (int kk = 0; kk < 16; kk++) {
            float a[8], b[8];
            #pragma unroll
            for (int i = 0; i < 8; i++) a[i] = As[kk][ty * 8 + i];
            #pragma unroll
            for (int j = 0; j < 8; j++) b[j] = Bs[kk][tx * 8 + j];
            #pragma unroll
            for (int i = 0; i < 8; i++)
                #pragma unroll
                for (int j = 0; j < 8; j++) acc[i][j] += a[i] * b[j];
        }
        __syncthreads();
    }
    #pragma unroll
    for (int i = 0; i < 8; i++) {
        #pragma unroll
        for (int j = 0; j < 8; j += 4) {
            float4 v = make_float4(acc[i][j], acc[i][j+1], acc[i][j+2], acc[i][j+3]);
            *(float4*)(g_h + (size_t)(bm + ty * 8 + i) * F_DIM + bn + tx * 8 + j) = v;
        }
    }
}

// ---------------- 2) f = h@a1, g = h@a2 ----------------
__global__ void fg_kernel(const float* __restrict__ a) {
    __shared__ float a1[F_DIM], a2[F_DIM];
    const int tid = threadIdx.x;                 // 256
    a1[tid] = a[tid];
    a2[tid] = a[F_DIM + tid];
    __syncthreads();
    const int warp = tid >> 5, lane = tid & 31;
    const int row = blockIdx.x * 8 + warp;
    const float* hr = g_h + (size_t)row * F_DIM;
    float sf = 0.f, sg = 0.f;
    #pragma unroll
    for (int c = lane; c < F_DIM; c += 32) {
        float v = hr[c];
        sf += v * a1[c];
        sg += v * a2[c];
    }
    #pragma unroll
    for (int o = 16; o > 0; o >>= 1) {
        sf += __shfl_down_sync(0xffffffffu, sf, o);
        sg += __shfl_down_sync(0xffffffffu, sg, o);
    }
    if (lane == 0) { g_f[row] = sf; g_g[row] = sg; }
}

// ---------------- 3) bitonic argsort of g (single block, smem) ----------------
__global__ void sort_kernel() {
    extern __shared__ float sm[];
    float* sk = sm;
    int*   si = (int*)(sm + N_ROWS);
    const int tid = threadIdx.x;   // 1024
    for (int i = tid; i < N_ROWS; i += 1024) { sk[i] = g_g[i]; si[i] = i; }
    __syncthreads();
    for (int k = 2; k <= N_ROWS; k <<= 1) {
        for (int j = k >> 1; j > 0; j >>= 1) {
            for (int t = tid; t < N_ROWS; t += 1024) {
                int ixj = t ^ j;
                if (ixj > t) {
                    bool up = ((t & k) == 0);
                    float av = sk[t], bv = sk[ixj];
                    bool swap = up ? (av > bv) : (av < bv);
                    if (swap) {
                        sk[t] = bv; sk[ixj] = av;
                        int tmp = si[t]; si[t] = si[ixj]; si[ixj] = tmp;
                    }
                }
            }
            __syncthreads();
        }
    }
    for (int i = tid; i < N_ROWS; i += 1024) { g_gs[i] = sk[i]; g_gidx[i] = si[i]; }
    if (tid == 0) g_scal[0] = sk[N_ROWS - 1];   // gmax
}

// ---------------- 4) scan phase 1: per-chunk partial sums ----------------
__global__ void scan1_kernel() {
    const int blk = blockIdx.x;     // 128
    const int c = threadIdx.x;      // 256
    const int base = blk * CHUNK;
    const float gmax = g_scal[0];
    float sH = 0.f, sE = 0.f, sW = 0.f;
    for (int r = 0; r < CHUNK; r++) {
        int row = g_gidx[base + r];
        float v = g_h[(size_t)row * F_DIM + c];
        float w = expf(g_gs[base + r] - gmax);
        sH += v;
        sE += w * v;
        sW += w;
    }
    g_pH[blk * F_DIM + c] = sH;
    g_pE[blk * F_DIM + c] = sE;
    if (c == 0) g_pW[blk] = sW;
}

// ---------------- 5) scan phase 2: cross-chunk offsets ----------------
__global__ void scan2_kernel() {
    const int c = threadIdx.x;      // 256
    float run = 0.f;
    for (int b = 0; b < NCHUNK; b++) {
        g_chOffH[b * F_DIM + c] = run;
        run += g_pH[b * F_DIM + c];
    }
    g_prefH[(size_t)N_ROWS * F_DIM + c] = run;   // total sum
    float runE = 0.f;
    for (int b = NCHUNK - 1; b >= 0; b--) {
        g_chOffE[b * F_DIM + c] = runE;
        runE += g_pE[b * F_DIM + c];
    }
    g_sufE[(size_t)N_ROWS * F_DIM + c] = 0.f;
    if (c == 0) {
        float rw = 0.f;
        for (int b = NCHUNK - 1; b >= 0; b--) { g_chOffW[b] = rw; rw += g_pW[b]; }
        g_sufW[N_ROWS] = 0.f;
    }
}

// ---------------- 6) scan phase 3: full prefix/suffix arrays ----------------
__global__ void scan3_kernel() {
    const int blk = blockIdx.x;     // 128
    const int c = threadIdx.x;      // 256
    const int base = blk * CHUNK;
    const float gmax = g_scal[0];
    float run = g_chOffH[blk * F_DIM + c];
    for (int r = 0; r < CHUNK; r++) {
        int k = base + r;
        g_prefH[(size_t)k * F_DIM + c] = run;
        run += g_h[(size_t)g_gidx[k] * F_DIM + c];
    }
    float runE = g_chOffE[blk * F_DIM + c];
    float runW = g_chOffW[blk];
    for (int r = CHUNK - 1; r >= 0; r--) {
        int k = base + r;
        float w = expf(g_gs[k] - gmax);
        runE += w * g_h[(size_t)g_gidx[k] * F_DIM + c];
        g_sufE[(size_t)k * F_DIM + c] = runE;
        runW += w;
        if (c == 0) g_sufW[k] = runW;
    }
}

// ---------------- 7) output: binary search + combine + elu ----------------
__global__ void out_kernel(float* __restrict__ out) {
    const int i = blockIdx.x;       // 8192 rows
    const int c = threadIdx.x;      // 256
    __shared__ int   s_k;
    __shared__ float s_alpha, s_beta, s_inv;
    if (c == 0) {
        float fi = g_f[i];
        float gmax = g_scal[0];
        float t = fi + gmax;
        float thr = -fi;
        int lo = 0, hi = N_ROWS;
        while (lo < hi) {
            int mid = (lo + hi) >> 1;
            if (g_gs[mid] <= thr) lo = mid + 1; else hi = mid;
        }
        int k = lo;                                  // count of g_j <= -f_i
        float alpha = expf(fminf(t, 0.f));           // exp(t - relu(t))
        float beta  = expf(-fmaxf(t, 0.f));          // exp(-relu(t))
        float denom = alpha * g_sufW[k] + beta * (float)k;
        s_k = k; s_alpha = alpha; s_beta = beta; s_inv = 1.f / denom;
    }
    __syncthreads();
    const int k = s_k;
    float num = s_alpha * g_sufE[(size_t)k * F_DIM + c]
              + s_beta  * g_prefH[(size_t)k * F_DIM + c];
    float y = num * s_inv;
    out[(size_t)i * F_DIM + c] = (y > 0.f) ? y : expm1f(y);
}

// ---------------- launch ----------------
extern "C" void kernel_launch(void* const* d_in, const int* in_sizes, int n_in,
                              void* d_out, int out_size) {
    const float* x = (const float*)d_in[0];   // [8192, 512]
    const float* W = (const float*)d_in[1];   // [512, 256]
    const float* a = (const float*)d_in[2];   // [512, 1]
    float* out = (float*)d_out;               // [8192, 256]

    gemm_h_kernel<<<dim3(F_DIM / 128, N_ROWS / 128), 256>>>(x, W);
    fg_kernel<<<N_ROWS / 8, 256>>>(a);

    cudaFuncSetAttribute(sort_kernel, cudaFuncAttributeMaxDynamicSharedMemorySize,
                         N_ROWS * 8);
    sort_kernel<<<1, 1024, N_ROWS * 8>>>();

    scan1_kernel<<<NCHUNK, F_DIM>>>();
    scan2_kernel<<<1, F_DIM>>>();
    scan3_kernel<<<NCHUNK, F_DIM>>>();
    out_kernel<<<N_ROWS, F_DIM>>>(out);
}

// round 2
// speedup vs baseline: 1.2357x; 1.2357x over previous
#include <cuda_runtime.h>
#include <math.h>

#define N_ROWS 8192
#define K_DIM  512
#define F_DIM  256
#define NCHUNK 256          // scan chunks
#define CHUNK  32           // rows per chunk (256*32 = 8192)

// ---------------- scratch (device globals) ----------------
__device__ float g_h[N_ROWS * F_DIM];            // h = x @ W
__device__ float g_f[N_ROWS];
__device__ float g_g[N_ROWS];
__device__ float g_gs[N_ROWS];                   // g sorted ascending
__device__ int   g_gidx[N_ROWS];                 // argsort
__device__ int   g_rank[N_ROWS];
__device__ float g_w[N_ROWS];                    // exp(gs - gmax)
__device__ float g_pH[NCHUNK * F_DIM];
__device__ float g_pE[NCHUNK * F_DIM];
__device__ float g_pW[NCHUNK];
__device__ float g_chOffH[NCHUNK * F_DIM];
__device__ float g_chOffE[NCHUNK * F_DIM];
__device__ float g_chOffW[NCHUNK];
__device__ float g_prefH[(N_ROWS + 1) * F_DIM];
__device__ float g_sufE[(N_ROWS + 1) * F_DIM];
__device__ float g_sufW[N_ROWS + 1];

// ---------------- 1) GEMM: h = x @ W (128x128 tile, f32x2 packed FMA) ----------------
__global__ void gemm_h_kernel(const float* __restrict__ x, const float* __restrict__ W) {
    __shared__ float As[16][128];   // [k][m]
    __shared__ float Bs[16][128];   // [k][n]
    const int bm = blockIdx.y * 128;
    const int bn = blockIdx.x * 128;
    const int tid = threadIdx.x;
    const int tx = tid & 15;
    const int ty = tid >> 4;

    unsigned long long acc2[8][4];  // 8 rows x 4 f32x2 pairs (= 8 cols)
    #pragma unroll
    for (int i = 0; i < 8; i++)
        #pragma unroll
        for (int j = 0; j < 4; j++) acc2[i][j] = 0ULL;  // bits of (0.f, 0.f)

    for (int k0 = 0; k0 < K_DIM; k0 += 16) {
        #pragma unroll
        for (int l = 0; l < 2; l++) {
            int idx = tid + l * 256;
            int r = idx >> 2;
            int c4 = (idx & 3) << 2;
            float4 v = *(const float4*)(x + (size_t)(bm + r) * K_DIM + k0 + c4);
            As[c4 + 0][r] = v.x; As[c4 + 1][r] = v.y;
            As[c4 + 2][r] = v.z; As[c4 + 3][r] = v.w;
        }
        #pragma unroll
        for (int l = 0; l < 2; l++) {
            int idx = tid + l * 256;
            int r = idx >> 5;
            int c4 = (idx & 31) << 2;
            *(float4*)&Bs[r][c4] = *(const float4*)(W + (size_t)(k0 + r) * F_DIM + bn + c4);
        }
        __syncthreads();
        #pragma unroll
        for (int kk = 0; kk < 16; kk++) {
            float a[8];
            #pragma unroll
            for (int i = 0; i < 8; i++) a[i] = As[kk][ty * 8 + i];
            unsigned long long b2[4];
            const unsigned long long* brow = (const unsigned long long*)(&Bs[kk][0]);
            #pragma unroll
            for (int j = 0; j < 4; j++) b2[j] = brow[tx * 4 + j];
            #pragma unroll
            for (int i = 0; i < 8; i++) {
                unsigned long long ai2;
                unsigned int abits = __float_as_uint(a[i]);
                asm("mov.b64 %0, {%1, %1};" : "=l"(ai2) : "r"(abits));
                #pragma unroll
                for (int j = 0; j < 4; j++) {
                    asm("fma.rn.f32x2 %0, %1, %2, %3;"
                        : "=l"(acc2[i][j]) : "l"(ai2), "l"(b2[j]), "l"(acc2[i][j]));
                }
            }
        }
        __syncthreads();
    }
    #pragma unroll
    for (int i = 0; i < 8; i++) {
        float c[8];
        #pragma unroll
        for (int j = 0; j < 4; j++) {
            unsigned int lo, hi;
            asm("mov.b64 {%0, %1}, %2;" : "=r"(lo), "=r"(hi) : "l"(acc2[i][j]));
            c[2 * j]     = __uint_as_float(lo);
            c[2 * j + 1] = __uint_as_float(hi);
        }
        float* dst = g_h + (size_t)(bm + ty * 8 + i) * F_DIM + bn + tx * 8;
        *(float4*)(dst)     = make_float4(c[0], c[1], c[2], c[3]);
        *(float4*)(dst + 4) = make_float4(c[4], c[5], c[6], c[7]);
    }
}

// ---------------- 2) f = h@a1, g = h@a2 (also zeroes g_rank) ----------------
__global__ void fg_kernel(const float* __restrict__ a) {
    __shared__ float a1[F_DIM], a2[F_DIM];
    const int tid = threadIdx.x;                 // 256
    a1[tid] = a[tid];
    a2[tid] = a[F_DIM + tid];
    __syncthreads();
    const int warp = tid >> 5, lane = tid & 31;
    const int row = blockIdx.x * 8 + warp;
    const float* hr = g_h + (size_t)row * F_DIM;
    float sf = 0.f, sg = 0.f;
    #pragma unroll
    for (int c = lane; c < F_DIM; c += 32) {
        float v = hr[c];
        sf += v * a1[c];
        sg += v * a2[c];
    }
    #pragma unroll
    for (int o = 16; o > 0; o >>= 1) {
        sf += __shfl_down_sync(0xffffffffu, sf, o);
        sg += __shfl_down_sync(0xffffffffu, sg, o);
    }
    if (lane == 0) { g_f[row] = sf; g_g[row] = sg; g_rank[row] = 0; }
}

// ---------------- 3a) rank-sort: count elements strictly before ----------------
__global__ void rank_kernel() {
    __shared__ float sj[1024];
    const int tid = threadIdx.x;        // 256
    const int bi = blockIdx.x;          // 32: i-chunk of 256
    const int bj = blockIdx.y;          // 8:  j-chunk of 1024
    const int jbase = bj * 1024;
    *(float4*)&sj[tid * 4] = *(const float4*)(g_g + jbase + tid * 4);
    __syncthreads();
    const int i = bi * 256 + tid;
    const float vi = g_g[i];
    int cnt = 0;
    #pragma unroll 4
    for (int jj = 0; jj < 1024; jj += 4) {
        float4 v = *(const float4*)&sj[jj];
        int j0 = jbase + jj;
        cnt += (v.x < vi) || (v.x == vi && (j0 + 0) < i);
        cnt += (v.y < vi) || (v.y == vi && (j0 + 1) < i);
        cnt += (v.z < vi) || (v.z == vi && (j0 + 2) < i);
        cnt += (v.w < vi) || (v.w == vi && (j0 + 3) < i);
    }
    atomicAdd(&g_rank[i], cnt);
}

// ---------------- 3b) scatter into sorted order ----------------
__global__ void scatter_kernel() {
    const int i = blockIdx.x * 256 + threadIdx.x;
    const int r = g_rank[i];
    g_gs[r] = g_g[i];
    g_gidx[r] = i;
}

// ---------------- 3c) precompute w = exp(gs - gmax) ----------------
__global__ void w_kernel() {
    const int k = blockIdx.x * 256 + threadIdx.x;
    const float gmax = g_gs[N_ROWS - 1];
    g_w[k] = expf(g_gs[k] - gmax);
}

// ---------------- 4) scan phase 1: per-chunk partial sums ----------------
__global__ void scan1_kernel() {
    __shared__ int   sidx[CHUNK];
    __shared__ float sw[CHUNK];
    const int blk = blockIdx.x;     // 256
    const int c = threadIdx.x;      // 256
    const int base = blk * CHUNK;
    if (c < CHUNK) { sidx[c] = g_gidx[base + c]; sw[c] = g_w[base + c]; }
    __syncthreads();
    float sH = 0.f, sE = 0.f, sW = 0.f;
    #pragma unroll
    for (int r = 0; r < CHUNK; r++) {
        float v = g_h[(size_t)sidx[r] * F_DIM + c];
        float w = sw[r];
        sH += v;
        sE += w * v;
        sW += w;
    }
    g_pH[blk * F_DIM + c] = sH;
    g_pE[blk * F_DIM + c] = sE;
    if (c == 0) g_pW[blk] = sW;
}

// ---------------- 5) scan phase 2: cross-chunk offsets ----------------
__global__ void scan2_kernel() {
    const int c = threadIdx.x;      // 256
    float run = 0.f;
    for (int b = 0; b < NCHUNK; b++) {
        g_chOffH[b * F_DIM + c] = run;
        run += g_pH[b * F_DIM + c];
    }
    g_prefH[(size_t)N_ROWS * F_DIM + c] = run;
    float runE = 0.f;
    for (int b = NCHUNK - 1; b >= 0; b--) {
        g_chOffE[b * F_DIM + c] = runE;
        runE += g_pE[b * F_DIM + c];
    }
    g_sufE[(size_t)N_ROWS * F_DIM + c] = 0.f;
    if (c == 0) {
        float rw = 0.f;
        for (int b = NCHUNK - 1; b >= 0; b--) { g_chOffW[b] = rw; rw += g_pW[b]; }
        g_sufW[N_ROWS] = 0.f;
    }
}

// ---------------- 6) scan phase 3: full prefix/suffix arrays ----------------
__global__ void scan3_kernel() {
    __shared__ int   sidx[CHUNK];
    __shared__ float sw[CHUNK];
    const int blk = blockIdx.x;     // 256
    const int c = threadIdx.x;      // 256
    const int base = blk * CHUNK;
    if (c < CHUNK) { sidx[c] = g_gidx[base + c]; sw[c] = g_w[base + c]; }
    __syncthreads();
    float run = g_chOffH[blk * F_DIM + c];
    #pragma unroll
    for (int r = 0; r < CHUNK; r++) {
        int k = base + r;
        g_prefH[(size_t)k * F_DIM + c] = run;
        run += g_h[(size_t)sidx[r] * F_DIM + c];
    }
    float runE = g_chOffE[blk * F_DIM + c];
    float runW = g_chOffW[blk];
    #pragma unroll
    for (int r = CHUNK - 1; r >= 0; r--) {
        int k = base + r;
        runE += sw[r] * g_h[(size_t)sidx[r] * F_DIM + c];
        g_sufE[(size_t)k * F_DIM + c] = runE;
        runW += sw[r];
        if (c == 0) g_sufW[k] = runW;
    }
}

// ---------------- 7) output: warp per row, binary search + combine + elu ----------------
__global__ void out_kernel(float* __restrict__ out) {
    const int warp = threadIdx.x >> 5, lane = threadIdx.x & 31;
    const int i = blockIdx.x * 8 + warp;
    int k; float alpha, beta, inv;
    if (lane == 0) {
        float fi = g_f[i];
        float gmax = g_gs[N_ROWS - 1];
        float t = fi + gmax;
        float thr = -fi;
        int lo = 0, hi = N_ROWS;
        while (lo < hi) {
            int mid = (lo + hi) >> 1;
            if (g_gs[mid] <= thr) lo = mid + 1; else hi = mid;
        }
        k = lo;
        alpha = expf(fminf(t, 0.f));
        beta  = expf(-fmaxf(t, 0.f));
        float denom = alpha * g_sufW[k] + beta * (float)k;
        inv = 1.f / denom;
    }
    k     = __shfl_sync(0xffffffffu, k, 0);
    alpha = __shfl_sync(0xffffffffu, alpha, 0);
    beta  = __shfl_sync(0xffffffffu, beta, 0);
    inv   = __shfl_sync(0xffffffffu, inv, 0);
    const float4* pe = (const float4*)(g_sufE  + (size_t)k * F_DIM);
    const float4* ph = (const float4*)(g_prefH + (size_t)k * F_DIM);
    float4* po = (float4*)(out + (size_t)i * F_DIM);
    #pragma unroll
    for (int j = 0; j < 2; j++) {
        int idx = lane + 32 * j;
        float4 e = pe[idx], h = ph[idx];
        float4 y;
        y.x = (alpha * e.x + beta * h.x) * inv;
        y.y = (alpha * e.y + beta * h.y) * inv;
        y.z = (alpha * e.z + beta * h.z) * inv;
        y.w = (alpha * e.w + beta * h.w) * inv;
        y.x = (y.x > 0.f) ? y.x : expm1f(y.x);
        y.y = (y.y > 0.f) ? y.y : expm1f(y.y);
        y.z = (y.z > 0.f) ? y.z : expm1f(y.z);
        y.w = (y.w > 0.f) ? y.w : expm1f(y.w);
        po[idx] = y;
    }
}

// ---------------- launch ----------------
extern "C" void kernel_launch(void* const* d_in, const int* in_sizes, int n_in,
                              void* d_out, int out_size) {
    const float* x = (const float*)d_in[0];   // [8192, 512]
    const float* W = (const float*)d_in[1];   // [512, 256]
    const float* a = (const float*)d_in[2];   // [512, 1]
    float* out = (float*)d_out;               // [8192, 256]

    gemm_h_kernel<<<dim3(F_DIM / 128, N_ROWS / 128), 256>>>(x, W);
    fg_kernel<<<N_ROWS / 8, 256>>>(a);
    rank_kernel<<<dim3(N_ROWS / 256, 8), 256>>>();
    scatter_kernel<<<N_ROWS / 256, 256>>>();
    w_kernel<<<N_ROWS / 256, 256>>>();
    scan1_kernel<<<NCHUNK, F_DIM>>>();
    scan2_kernel<<<1, F_DIM>>>();
    scan3_kernel<<<NCHUNK, F_DIM>>>();
    out_kernel<<<N_ROWS / 8, F_DIM>>>(out);
}

// round 4
// speedup vs baseline: 2.7773x; 2.2475x over previous
#include <cuda_runtime.h>
#include <cuda_bf16.h>
#include <math.h>
#include <cstdint>

#define N_ROWS 8192
#define K_DIM  512
#define F_DIM  256
#define NCHUNK 512
#define CHUNK  16

// ---------------- scratch (device globals) ----------------
__device__ __nv_bfloat16 g_xh[N_ROWS * K_DIM];
__device__ __nv_bfloat16 g_xl[N_ROWS * K_DIM];
__device__ __nv_bfloat16 g_wth[F_DIM * K_DIM];   // W^T hi  [256][512]
__device__ __nv_bfloat16 g_wtl[F_DIM * K_DIM];   // W^T lo
__device__ float g_h[N_ROWS * F_DIM];
__device__ float g_f[N_ROWS];
__device__ float g_g[N_ROWS];
__device__ unsigned g_gmax_u;
__device__ float g_gs[N_ROWS];
__device__ int   g_gidx[N_ROWS];
__device__ int   g_rank[N_ROWS];
__device__ float g_w[N_ROWS];
__device__ float g_pH[NCHUNK * F_DIM];
__device__ float g_pE[NCHUNK * F_DIM];
__device__ float g_pW[NCHUNK];
__device__ float g_chOffH[NCHUNK * F_DIM];
__device__ float g_chOffE[NCHUNK * F_DIM];
__device__ float g_chOffW[NCHUNK];
__device__ float g_prefH[(N_ROWS + 1) * F_DIM];
__device__ float g_sufE[(N_ROWS + 1) * F_DIM];
__device__ float g_sufW[N_ROWS + 1];

// ---------------- helpers ----------------
__device__ __forceinline__ uint32_t smem_u32(const void* p) {
    uint32_t a;
    asm("{ .reg .u64 t; cvta.to.shared.u64 t, %1; cvt.u32.u64 %0, t; }" : "=r"(a) : "l"(p));
    return a;
}
__device__ __forceinline__ unsigned f2mono(float f) {
    unsigned b = __float_as_uint(f);
    return (b & 0x80000000u) ? ~b : (b | 0x80000000u);
}
__device__ __forceinline__ float mono2f(unsigned u) {
    return (u & 0x80000000u) ? __uint_as_float(u & 0x7fffffffu) : __uint_as_float(~u);
}
__device__ __forceinline__ void ldsm_x4(uint32_t (&r)[4], uint32_t addr) {
    asm volatile("ldmatrix.sync.aligned.m8n8.x4.shared.b16 {%0,%1,%2,%3}, [%4];"
                 : "=r"(r[0]), "=r"(r[1]), "=r"(r[2]), "=r"(r[3]) : "r"(addr));
}
__device__ __forceinline__ void mma16816(float (&d)[4], const uint32_t (&a)[4],
                                         uint32_t b0, uint32_t b1) {
    asm volatile(
        "mma.sync.aligned.m16n8k16.row.col.f32.bf16.bf16.f32 "
        "{%0,%1,%2,%3}, {%4,%5,%6,%7}, {%8,%9}, {%0,%1,%2,%3};"
        : "+f"(d[0]), "+f"(d[1]), "+f"(d[2]), "+f"(d[3])
        : "r"(a[0]), "r"(a[1]), "r"(a[2]), "r"(a[3]), "r"(b0), "r"(b1));
}
__device__ __forceinline__ void cp16(uint32_t dst, const void* src) {
    asm volatile("cp.async.cg.shared.global [%0], [%1], 16;" :: "r"(dst), "l"(src));
}

// ---------------- 0a) convert x -> (xh, xl) ----------------
__global__ void convert_x_kernel(const float* __restrict__ x) {
    const int idx = (blockIdx.x * 256 + threadIdx.x) * 4;
    float4 v = *(const float4*)(x + idx);
    __nv_bfloat16 h0 = __float2bfloat16_rn(v.x), h1 = __float2bfloat16_rn(v.y);
    __nv_bfloat16 h2 = __float2bfloat16_rn(v.z), h3 = __float2bfloat16_rn(v.w);
    __nv_bfloat16 l0 = __float2bfloat16_rn(v.x - __bfloat162float(h0));
    __nv_bfloat16 l1 = __float2bfloat16_rn(v.y - __bfloat162float(h1));
    __nv_bfloat16 l2 = __float2bfloat16_rn(v.z - __bfloat162float(h2));
    __nv_bfloat16 l3 = __float2bfloat16_rn(v.w - __bfloat162float(h3));
    __nv_bfloat162* ph = (__nv_bfloat162*)(g_xh + idx);
    __nv_bfloat162* pl = (__nv_bfloat162*)(g_xl + idx);
    ph[0] = __nv_bfloat162(h0, h1); ph[1] = __nv_bfloat162(h2, h3);
    pl[0] = __nv_bfloat162(l0, l1); pl[1] = __nv_bfloat162(l2, l3);
}

// ---------------- 0b) convert + transpose W; init rank/gmax ----------------
__global__ void convert_w_kernel(const float* __restrict__ W) {
    const int idx = blockIdx.x * 256 + threadIdx.x;   // 512*256
    if (idx == 0) g_gmax_u = 0;
    if (idx < N_ROWS) g_rank[idx] = 0;
    const int k = idx >> 8;
    const int n = idx & 255;
    float v = W[idx];
    __nv_bfloat16 h = __float2bfloat16_rn(v);
    __nv_bfloat16 l = __float2bfloat16_rn(v - __bfloat162float(h));
    g_wth[(size_t)n * K_DIM + k] = h;
    g_wtl[(size_t)n * K_DIM + k] = l;
}

// ---------------- 1) mma.sync GEMM: h = x @ W  (bf16 3-term split) ----------------
// CTA tile: 128(M) x 128(N), K-chunks of 64, 256 threads (8 warps 2x4).
// SMEM per buffer: AH, AL (128 rows x 64 cols, stride 72 bf16) then BH, BL
// (128 n-rows x 64 k-cols, stride 72 bf16). Buffer size 4*18432 = 73728 B.
#define GSTRIDE 72
#define TILE_B  18432
#define BUFSZ   73728

__device__ __forceinline__ void load_chunk_async(uint32_t sb, int buf, int k0,
                                                 int bm, int bn, int tid) {
    uint32_t base = sb + buf * BUFSZ;
    #pragma unroll
    for (int l = 0; l < 4; l++) {
        int idx = tid + l * 256;
        int r = idx >> 3, c8 = (idx & 7) * 8;
        uint32_t off = (uint32_t)(r * GSTRIDE + c8) * 2;
        const __nv_bfloat16* xs = g_xh + (size_t)(bm + r) * K_DIM + k0 + c8;
        const __nv_bfloat16* xl = g_xl + (size_t)(bm + r) * K_DIM + k0 + c8;
        const __nv_bfloat16* wh = g_wth + (size_t)(bn + r) * K_DIM + k0 + c8;
        const __nv_bfloat16* wl = g_wtl + (size_t)(bn + r) * K_DIM + k0 + c8;
        cp16(base + off, xs);
        cp16(base + TILE_B + off, xl);
        cp16(base + 2 * TILE_B + off, wh);
        cp16(base + 3 * TILE_B + off, wl);
    }
}

__global__ void __launch_bounds__(256, 1) gemm_mma_kernel() {
    extern __shared__ char smem[];
    const uint32_t sb = smem_u32(smem);
    const int tid = threadIdx.x;
    const int wid = tid >> 5, lane = tid & 31;
    const int warp_m = wid >> 2;          // 0..1
    const int warp_n = wid & 3;           // 0..3
    const int bm = blockIdx.y * 128;
    const int bn = blockIdx.x * 128;

    float acc[4][4][4];
    #pragma unroll
    for (int mt = 0; mt < 4; mt++)
        #pragma unroll
        for (int nt = 0; nt < 4; nt++)
            #pragma unroll
            for (int r = 0; r < 4; r++) acc[mt][nt][r] = 0.f;

    // ldmatrix address offsets (element units)
    const int a_row = warp_m * 64 + (lane & 15);
    const int a_col = (lane >> 4) * 8;
    const int b_row = warp_n * 32 + ((lane >> 4) & 1) * 8 + (lane & 7);
    const int b_col = ((lane >> 3) & 1) * 8;

    load_chunk_async(sb, 0, 0, bm, bn, tid);
    asm volatile("cp.async.commit_group;" ::: "memory");

    for (int i = 0; i < 8; i++) {
        asm volatile("cp.async.wait_group 0;" ::: "memory");
        __syncthreads();
        if (i < 7) {
            load_chunk_async(sb, (i & 1) ^ 1, (i + 1) * 64, bm, bn, tid);
            asm volatile("cp.async.commit_group;" ::: "memory");
        }
        const uint32_t bufb = sb + (i & 1) * BUFSZ;
        #pragma unroll
        for (int kk = 0; kk < 4; kk++) {
            uint32_t ah[4][4], al[4][4], bh[2][4], bl[2][4];
            #pragma unroll
            for (int mt = 0; mt < 4; mt++) {
                uint32_t off = (uint32_t)((a_row + mt * 16) * GSTRIDE + kk * 16 + a_col) * 2;
                ldsm_x4(ah[mt], bufb + off);
                ldsm_x4(al[mt], bufb + TILE_B + off);
            }
            #pragma unroll
            for (int np = 0; np < 2; np++) {
                uint32_t off = (uint32_t)((b_row + np * 16) * GSTRIDE + kk * 16 + b_col) * 2;
                ldsm_x4(bh[np], bufb + 2 * TILE_B + off);
                ldsm_x4(bl[np], bufb + 3 * TILE_B + off);
            }
            #pragma unroll
            for (int mt = 0; mt < 4; mt++) {
                #pragma unroll
                for (int nt = 0; nt < 4; nt++) {
                    int np = nt >> 1, p = (nt & 1) * 2;
                    mma16816(acc[mt][nt], ah[mt], bh[np][p], bh[np][p + 1]);
                    mma16816(acc[mt][nt], ah[mt], bl[np][p], bl[np][p + 1]);
                    mma16816(acc[mt][nt], al[mt], bh[np][p], bh[np][p + 1]);
                }
            }
        }
        __syncthreads();
    }

    // epilogue: write h
    const int g = lane >> 2, t = lane & 3;
    #pragma unroll
    for (int mt = 0; mt < 4; mt++) {
        #pragma unroll
        for (int nt = 0; nt < 4; nt++) {
            int row = bm + warp_m * 64 + mt * 16 + g;
            int col = bn + warp_n * 32 + nt * 8 + t * 2;
            *(float2*)(g_h + (size_t)row * F_DIM + col) =
                make_float2(acc[mt][nt][0], acc[mt][nt][1]);
            *(float2*)(g_h + (size_t)(row + 8) * F_DIM + col) =
                make_float2(acc[mt][nt][2], acc[mt][nt][3]);
        }
    }
}

// ---------------- 2) f = h@a1, g = h@a2, gmax ----------------
__global__ void fg_kernel(const float* __restrict__ a) {
    __shared__ float a1[F_DIM], a2[F_DIM];
    const int tid = threadIdx.x;                 // 256
    a1[tid] = a[tid];
    a2[tid] = a[F_DIM + tid];
    __syncthreads();
    const int warp = tid >> 5, lane = tid & 31;
    const int row = blockIdx.x * 8 + warp;
    const float* hr = g_h + (size_t)row * F_DIM;
    float sf = 0.f, sg = 0.f;
    #pragma unroll
    for (int c = lane; c < F_DIM; c += 32) {
        float v = hr[c];
        sf += v * a1[c];
        sg += v * a2[c];
    }
    #pragma unroll
    for (int o = 16; o > 0; o >>= 1) {
        sf += __shfl_down_sync(0xffffffffu, sf, o);
        sg += __shfl_down_sync(0xffffffffu, sg, o);
    }
    if (lane == 0) {
        g_f[row] = sf;
        g_g[row] = sg;
        atomicMax(&g_gmax_u, f2mono(sg));
    }
}

// ---------------- 3a) rank-sort ----------------
__global__ void rank_kernel() {
    __shared__ float sj[1024];
    const int tid = threadIdx.x;
    const int bi = blockIdx.x;
    const int bj = blockIdx.y;
    const int jbase = bj * 1024;
    *(float4*)&sj[tid * 4] = *(const float4*)(g_g + jbase + tid * 4);
    __syncthreads();
    const int i = bi * 256 + tid;
    const float vi = g_g[i];
    int cnt = 0;
    #pragma unroll 4
    for (int jj = 0; jj < 1024; jj += 4) {
        float4 v = *(const float4*)&sj[jj];
        int j0 = jbase + jj;
        cnt += (v.x < vi) || (v.x == vi && (j0 + 0) < i);
        cnt += (v.y < vi) || (v.y == vi && (j0 + 1) < i);
        cnt += (v.z < vi) || (v.z == vi && (j0 + 2) < i);
        cnt += (v.w < vi) || (v.w == vi && (j0 + 3) < i);
    }
    atomicAdd(&g_rank[i], cnt);
}

// ---------------- 3b) scatter + w ----------------
__global__ void scatter_kernel() {
    const int i = blockIdx.x * 256 + threadIdx.x;
    const int r = g_rank[i];
    const float gi = g_g[i];
    const float gmax = mono2f(g_gmax_u);
    g_gs[r] = gi;
    g_gidx[r] = i;
    g_w[r] = expf(gi - gmax);
}

// ---------------- 4) scan phase 1: per-chunk partial sums ----------------
__global__ void scan1_kernel() {
    __shared__ int   sidx[CHUNK];
    __shared__ float sw[CHUNK];
    const int blk = blockIdx.x;
    const int c = threadIdx.x;
    const int base = blk * CHUNK;
    if (c < CHUNK) { sidx[c] = g_gidx[base + c]; sw[c] = g_w[base + c]; }
    __syncthreads();
    float sH = 0.f, sE = 0.f, sW = 0.f;
    #pragma unroll
    for (int r = 0; r < CHUNK; r++) {
        float v = g_h[(size_t)sidx[r] * F_DIM + c];
        float w = sw[r];
        sH += v; sE += w * v; sW += w;
    }
    g_pH[blk * F_DIM + c] = sH;
    g_pE[blk * F_DIM + c] = sE;
    if (c == 0) g_pW[blk] = sW;
}

// ---------------- 5) scan phase 2: warp-per-column cross-chunk scan ----------------
__global__ void scan2_kernel() {   // grid 32 x 256 threads
    const unsigned FULL = 0xffffffffu;
    const int warp = threadIdx.x >> 5, lane = threadIdx.x & 31;
    const int c = blockIdx.x * 8 + warp;   // 0..255
    float carry = 0.f;
    for (int s = 0; s < NCHUNK; s += 32) {
        float v = g_pH[(s + lane) * F_DIM + c];
        float x = v;
        #pragma unroll
        for (int o = 1; o < 32; o <<= 1) {
            float t = __shfl_up_sync(FULL, x, o);
            if (lane >= o) x += t;
        }
        g_chOffH[(s + lane) * F_DIM + c] = carry + x - v;
        carry += __shfl_sync(FULL, x, 31);
    }
    g_prefH[(size_t)N_ROWS * F_DIM + c] = carry;
    float carryE = 0.f;
    for (int s = NCHUNK - 32; s >= 0; s -= 32) {
        float v = g_pE[(s + lane) * F_DIM + c];
        float x = v;
        #pragma unroll
        for (int o = 1; o < 32; o <<= 1) {
            float t = __shfl_down_sync(FULL, x, o);
            if (lane + o < 32) x += t;
        }
        g_chOffE[(s + lane) * F_DIM + c] = carryE + x - v;
        carryE += __shfl_sync(FULL, x, 0);
    }
    g_sufE[(size_t)N_ROWS * F_DIM + c] = 0.f;
    if (blockIdx.x == 0 && warp == 0) {
        float cw = 0.f;
        for (int s = NCHUNK - 32; s >= 0; s -= 32) {
            float v = g_pW[s + lane];
            float x = v;
            #pragma unroll
            for (int o = 1; o < 32; o <<= 1) {
                float t = __shfl_down_sync(FULL, x, o);
                if (lane + o < 32) x += t;
            }
            g_chOffW[s + lane] = cw + x - v;
            cw += __shfl_sync(FULL, x, 0);
        }
        if (lane == 0) g_sufW[N_ROWS] = 0.f;
    }
}

// ---------------- 6) scan phase 3: full prefix/suffix arrays ----------------
__global__ void scan3_kernel() {
    __shared__ int   sidx[CHUNK];
    __shared__ float sw[CHUNK];
    const int blk = blockIdx.x;
    const int c = threadIdx.x;
    const int base = blk * CHUNK;
    if (c < CHUNK) { sidx[c] = g_gidx[base + c]; sw[c] = g_w[base + c]; }
    __syncthreads();
    float run = g_chOffH[blk * F_DIM + c];
    #pragma unroll
    for (int r = 0; r < CHUNK; r++) {
        int k = base + r;
        g_prefH[(size_t)k * F_DIM + c] = run;
        run += g_h[(size_t)sidx[r] * F_DIM + c];
    }
    float runE = g_chOffE[blk * F_DIM + c];
    float runW = g_chOffW[blk];
    #pragma unroll
    for (int r = CHUNK - 1; r >= 0; r--) {
        int k = base + r;
        runE += sw[r] * g_h[(size_t)sidx[r] * F_DIM + c];
        g_sufE[(size_t)k * F_DIM + c] = runE;
        runW += sw[r];
        if (c == 0) g_sufW[k] = runW;
    }
}

// ---------------- 7) output ----------------
__global__ void out_kernel(float* __restrict__ out) {
    const int warp = threadIdx.x >> 5, lane = threadIdx.x & 31;
    const int i = blockIdx.x * 8 + warp;
    int k; float alpha, beta, inv;
    if (lane == 0) {
        float fi = g_f[i];
        float gmax = g_gs[N_ROWS - 1];
        float t = fi + gmax;
        float thr = -fi;
        int lo = 0, hi = N_ROWS;
        while (lo < hi) {
            int mid = (lo + hi) >> 1;
            if (g_gs[mid] <= thr) lo = mid + 1; else hi = mid;
        }
        k = lo;
        alpha = expf(fminf(t, 0.f));
        beta  = expf(-fmaxf(t, 0.f));
        inv = 1.f / (alpha * g_sufW[k] + beta * (float)k);
    }
    k     = __shfl_sync(0xffffffffu, k, 0);
    alpha = __shfl_sync(0xffffffffu, alpha, 0);
    beta  = __shfl_sync(0xffffffffu, beta, 0);
    inv   = __shfl_sync(0xffffffffu, inv, 0);
    const float4* pe = (const float4*)(g_sufE  + (size_t)k * F_DIM);
    const float4* ph = (const float4*)(g_prefH + (size_t)k * F_DIM);
    float4* po = (float4*)(out + (size_t)i * F_DIM);
    #pragma unroll
    for (int j = 0; j < 2; j++) {
        int idx = lane + 32 * j;
        float4 e = pe[idx], h = ph[idx];
        float4 y;
        y.x = (alpha * e.x + beta * h.x) * inv;
        y.y = (alpha * e.y + beta * h.y) * inv;
        y.z = (alpha * e.z + beta * h.z) * inv;
        y.w = (alpha * e.w + beta * h.w) * inv;
        y.x = (y.x > 0.f) ? y.x : expm1f(y.x);
        y.y = (y.y > 0.f) ? y.y : expm1f(y.y);
        y.z = (y.z > 0.f) ? y.z : expm1f(y.z);
        y.w = (y.w > 0.f) ? y.w : expm1f(y.w);
        po[idx] = y;
    }
}

// ---------------- launch ----------------
extern "C" void kernel_launch(void* const* d_in, const int* in_sizes, int n_in,
                              void* d_out, int out_size) {
    const float* x = (const float*)d_in[0];
    const float* W = (const float*)d_in[1];
    const float* a = (const float*)d_in[2];
    float* out = (float*)d_out;

    convert_x_kernel<<<N_ROWS * K_DIM / 1024, 256>>>(x);
    convert_w_kernel<<<K_DIM * F_DIM / 256, 256>>>(W);

    cudaFuncSetAttribute(gemm_mma_kernel,
                         cudaFuncAttributeMaxDynamicSharedMemorySize, 2 * BUFSZ);
    gemm_mma_kernel<<<dim3(F_DIM / 128, N_ROWS / 128), 256, 2 * BUFSZ>>>();

    fg_kernel<<<N_ROWS / 8, 256>>>(a);
    rank_kernel<<<dim3(N_ROWS / 256, 8), 256>>>();
    scatter_kernel<<<N_ROWS / 256, 256>>>();
    scan1_kernel<<<NCHUNK, F_DIM>>>();
    scan2_kernel<<<32, 256>>>();
    scan3_kernel<<<NCHUNK, F_DIM>>>();
    out_kernel<<<N_ROWS / 8, 256>>>(out);
}

// round 6
// speedup vs baseline: 3.0250x; 1.0892x over previous
#include <cuda_runtime.h>
#include <cuda_bf16.h>
#include <math.h>
#include <cstdint>

#define N_ROWS 8192
#define K_DIM  512
#define F_DIM  256
#define NCHUNK 512
#define CHUNK  16

// ---------------- scratch (device globals) ----------------
__device__ __nv_bfloat16 g_xh[N_ROWS * K_DIM];
__device__ __nv_bfloat16 g_xl[N_ROWS * K_DIM];
__device__ __nv_bfloat16 g_wth[F_DIM * K_DIM];   // W^T hi  [256][512]
__device__ __nv_bfloat16 g_wtl[F_DIM * K_DIM];   // W^T lo
__device__ float g_h[N_ROWS * F_DIM];
__device__ float g_f[N_ROWS];
__device__ float g_g[N_ROWS];
__device__ unsigned g_gmax_u;
__device__ float g_gs[N_ROWS];
__device__ int   g_gidx[N_ROWS];
__device__ int   g_rank[N_ROWS];
__device__ float g_w[N_ROWS];
__device__ float g_pH[NCHUNK * F_DIM];
__device__ float g_pE[NCHUNK * F_DIM];
__device__ float g_pW[NCHUNK];
__device__ float g_chOffH[NCHUNK * F_DIM];
__device__ float g_chOffE[NCHUNK * F_DIM];
__device__ float g_chOffW[NCHUNK];
__device__ float g_prefH[(N_ROWS + 1) * F_DIM];
__device__ float g_sufE[(N_ROWS + 1) * F_DIM];
__device__ float g_sufW[N_ROWS + 1];

// ---------------- helpers ----------------
__device__ __forceinline__ uint32_t smem_u32(const void* p) {
    uint32_t a;
    asm("{ .reg .u64 t; cvta.to.shared.u64 t, %1; cvt.u32.u64 %0, t; }" : "=r"(a) : "l"(p));
    return a;
}
__device__ __forceinline__ unsigned f2mono(float f) {
    unsigned b = __float_as_uint(f);
    return (b & 0x80000000u) ? ~b : (b | 0x80000000u);
}
__device__ __forceinline__ float mono2f(unsigned u) {
    return (u & 0x80000000u) ? __uint_as_float(u & 0x7fffffffu) : __uint_as_float(~u);
}
__device__ __forceinline__ void ldsm_x4(uint32_t (&r)[4], uint32_t addr) {
    asm volatile("ldmatrix.sync.aligned.m8n8.x4.shared.b16 {%0,%1,%2,%3}, [%4];"
                 : "=r"(r[0]), "=r"(r[1]), "=r"(r[2]), "=r"(r[3]) : "r"(addr));
}
__device__ __forceinline__ void mma16816(float (&d)[4], const uint32_t (&a)[4],
                                         uint32_t b0, uint32_t b1) {
    asm volatile(
        "mma.sync.aligned.m16n8k16.row.col.f32.bf16.bf16.f32 "
        "{%0,%1,%2,%3}, {%4,%5,%6,%7}, {%8,%9}, {%0,%1,%2,%3};"
        : "+f"(d[0]), "+f"(d[1]), "+f"(d[2]), "+f"(d[3])
        : "r"(a[0]), "r"(a[1]), "r"(a[2]), "r"(a[3]), "r"(b0), "r"(b1));
}
__device__ __forceinline__ void cp16(uint32_t dst, const void* src) {
    asm volatile("cp.async.cg.shared.global [%0], [%1], 16;" :: "r"(dst), "l"(src));
}

// ---------------- 0) fused convert: x -> (xh,xl), W -> (Wth,Wtl), zero-inits ----
#define XBLOCKS (N_ROWS * K_DIM / 1024)   // 4096
#define WBLOCKS (K_DIM * F_DIM / 256)     // 512
__global__ void convert_kernel(const float* __restrict__ x, const float* __restrict__ W) {
    if (blockIdx.x < XBLOCKS) {
        const int idx = (blockIdx.x * 256 + threadIdx.x) * 4;
        float4 v = *(const float4*)(x + idx);
        __nv_bfloat16 h0 = __float2bfloat16_rn(v.x), h1 = __float2bfloat16_rn(v.y);
        __nv_bfloat16 h2 = __float2bfloat16_rn(v.z), h3 = __float2bfloat16_rn(v.w);
        __nv_bfloat16 l0 = __float2bfloat16_rn(v.x - __bfloat162float(h0));
        __nv_bfloat16 l1 = __float2bfloat16_rn(v.y - __bfloat162float(h1));
        __nv_bfloat16 l2 = __float2bfloat16_rn(v.z - __bfloat162float(h2));
        __nv_bfloat16 l3 = __float2bfloat16_rn(v.w - __bfloat162float(h3));
        __nv_bfloat162* ph = (__nv_bfloat162*)(g_xh + idx);
        __nv_bfloat162* pl = (__nv_bfloat162*)(g_xl + idx);
        ph[0] = __nv_bfloat162(h0, h1); ph[1] = __nv_bfloat162(h2, h3);
        pl[0] = __nv_bfloat162(l0, l1); pl[1] = __nv_bfloat162(l2, l3);
    } else {
        const int idx = (blockIdx.x - XBLOCKS) * 256 + threadIdx.x;  // 0..131071
        if (idx == 0) g_gmax_u = 0;
        if (idx < N_ROWS) { g_rank[idx] = 0; g_f[idx] = 0.f; g_g[idx] = 0.f; }
        const int k = idx >> 8;
        const int n = idx & 255;
        float v = W[idx];
        __nv_bfloat16 h = __float2bfloat16_rn(v);
        __nv_bfloat16 l = __float2bfloat16_rn(v - __bfloat162float(h));
        g_wth[(size_t)n * K_DIM + k] = h;
        g_wtl[(size_t)n * K_DIM + k] = l;
    }
}

// ---------------- 1) mma.sync GEMM: h = x @ W (+ fused f/g partials) ----------------
#define GSTRIDE 72
#define TILE_B  18432
#define BUFSZ   73728
#define SM_A1A2 (2 * BUFSZ)

__device__ __forceinline__ void load_chunk_async(uint32_t sb, int buf, int k0,
                                                 int bm, int bn, int tid) {
    uint32_t base = sb + buf * BUFSZ;
    #pragma unroll
    for (int l = 0; l < 4; l++) {
        int idx = tid + l * 256;
        int r = idx >> 3, c8 = (idx & 7) * 8;
        uint32_t off = (uint32_t)(r * GSTRIDE + c8) * 2;
        cp16(base + off,              g_xh  + (size_t)(bm + r) * K_DIM + k0 + c8);
        cp16(base + TILE_B + off,     g_xl  + (size_t)(bm + r) * K_DIM + k0 + c8);
        cp16(base + 2 * TILE_B + off, g_wth + (size_t)(bn + r) * K_DIM + k0 + c8);
        cp16(base + 3 * TILE_B + off, g_wtl + (size_t)(bn + r) * K_DIM + k0 + c8);
    }
}

__global__ void __launch_bounds__(256, 1) gemm_mma_kernel(const float* __restrict__ a) {
    extern __shared__ char smem[];
    const uint32_t sb = smem_u32(smem);
    float* sa = (float*)(smem + SM_A1A2);
    const int tid = threadIdx.x;
    const int wid = tid >> 5, lane = tid & 31;
    const int warp_m = wid >> 2;
    const int warp_n = wid & 3;
    const int bm = blockIdx.y * 128;
    const int bn = blockIdx.x * 128;

    float acc[4][4][4];
    #pragma unroll
    for (int mt = 0; mt < 4; mt++)
        #pragma unroll
        for (int nt = 0; nt < 4; nt++)
            #pragma unroll
            for (int r = 0; r < 4; r++) acc[mt][nt][r] = 0.f;

    const int a_row = warp_m * 64 + (lane & 15);
    const int a_col = (lane >> 4) * 8;
    const int b_row = warp_n * 32 + ((lane >> 4) & 1) * 8 + (lane & 7);
    const int b_col = ((lane >> 3) & 1) * 8;

    sa[tid] = a[tid];
    sa[256 + tid] = a[256 + tid];
    load_chunk_async(sb, 0, 0, bm, bn, tid);
    asm volatile("cp.async.commit_group;" ::: "memory");

    for (int i = 0; i < 8; i++) {
        asm volatile("cp.async.wait_group 0;" ::: "memory");
        __syncthreads();
        if (i < 7) {
            load_chunk_async(sb, (i & 1) ^ 1, (i + 1) * 64, bm, bn, tid);
            asm volatile("cp.async.commit_group;" ::: "memory");
        }
        const uint32_t bufb = sb + (i & 1) * BUFSZ;
        #pragma unroll
        for (int kk = 0; kk < 4; kk++) {
            uint32_t ah[4][4], al[4][4], bh[2][4], bl[2][4];
            #pragma unroll
            for (int mt = 0; mt < 4; mt++) {
                uint32_t off = (uint32_t)((a_row + mt * 16) * GSTRIDE + kk * 16 + a_col) * 2;
                ldsm_x4(ah[mt], bufb + off);
                ldsm_x4(al[mt], bufb + TILE_B + off);
            }
            #pragma unroll
            for (int np = 0; np < 2; np++) {
                uint32_t off = (uint32_t)((b_row + np * 16) * GSTRIDE + kk * 16 + b_col) * 2;
                ldsm_x4(bh[np], bufb + 2 * TILE_B + off);
                ldsm_x4(bl[np], bufb + 3 * TILE_B + off);
            }
            #pragma unroll
            for (int mt = 0; mt < 4; mt++) {
                #pragma unroll
                for (int nt = 0; nt < 4; nt++) {
                    int np = nt >> 1, p = (nt & 1) * 2;
                    mma16816(acc[mt][nt], ah[mt], bh[np][p], bh[np][p + 1]);
                    mma16816(acc[mt][nt], ah[mt], bl[np][p], bl[np][p + 1]);
                    mma16816(acc[mt][nt], al[mt], bh[np][p], bh[np][p + 1]);
                }
            }
        }
        __syncthreads();
    }

    // epilogue: write h + fused f/g partial dot products
    const int g = lane >> 2, t = lane & 3;
    #pragma unroll
    for (int mt = 0; mt < 4; mt++) {
        const int row = bm + warp_m * 64 + mt * 16 + g;
        float f0 = 0.f, g0 = 0.f, f1 = 0.f, g1 = 0.f;
        #pragma unroll
        for (int nt = 0; nt < 4; nt++) {
            const int colS = bn + warp_n * 32 + nt * 8 + t * 2;  // global col in [0,256)
            const float a1c0 = sa[colS],       a1c1 = sa[colS + 1];
            const float a2c0 = sa[256 + colS], a2c1 = sa[256 + colS + 1];
            *(float2*)(g_h + (size_t)row * F_DIM + colS) =
                make_float2(acc[mt][nt][0], acc[mt][nt][1]);
            *(float2*)(g_h + (size_t)(row + 8) * F_DIM + colS) =
                make_float2(acc[mt][nt][2], acc[mt][nt][3]);
            f0 += acc[mt][nt][0] * a1c0 + acc[mt][nt][1] * a1c1;
            g0 += acc[mt][nt][0] * a2c0 + acc[mt][nt][1] * a2c1;
            f1 += acc[mt][nt][2] * a1c0 + acc[mt][nt][3] * a1c1;
            g1 += acc[mt][nt][2] * a2c0 + acc[mt][nt][3] * a2c1;
        }
        #pragma unroll
        for (int o = 1; o < 4; o <<= 1) {
            f0 += __shfl_xor_sync(0xffffffffu, f0, o);
            g0 += __shfl_xor_sync(0xffffffffu, g0, o);
            f1 += __shfl_xor_sync(0xffffffffu, f1, o);
            g1 += __shfl_xor_sync(0xffffffffu, g1, o);
        }
        if (t == 0) {
            atomicAdd(g_f + row, f0);
            atomicAdd(g_g + row, g0);
            atomicAdd(g_f + row + 8, f1);
            atomicAdd(g_g + row + 8, g1);
        }
    }
}

// ---------------- 3a) rank-sort (+ gmax on bj==0) ----------------
__global__ void rank_kernel() {
    __shared__ float sj[1024];
    const int tid = threadIdx.x;
    const int bi = blockIdx.x;
    const int bj = blockIdx.y;
    const int jbase = bj * 1024;
    *(float4*)&sj[tid * 4] = *(const float4*)(g_g + jbase + tid * 4);
    __syncthreads();
    const int i = bi * 256 + tid;
    const float vi = g_g[i];
    int cnt = 0;
    #pragma unroll 4
    for (int jj = 0; jj < 1024; jj += 4) {
        float4 v = *(const float4*)&sj[jj];
        int j0 = jbase + jj;
        cnt += (v.x < vi) || (v.x == vi && (j0 + 0) < i);
        cnt += (v.y < vi) || (v.y == vi && (j0 + 1) < i);
        cnt += (v.z < vi) || (v.z == vi && (j0 + 2) < i);
        cnt += (v.w < vi) || (v.w == vi && (j0 + 3) < i);
    }
    atomicAdd(&g_rank[i], cnt);
    if (bj == 0) {
        unsigned mu = f2mono(vi);
        #pragma unroll
        for (int o = 16; o > 0; o >>= 1)
            mu = max(mu, __shfl_xor_sync(0xffffffffu, mu, o));
        if ((tid & 31) == 0) atomicMax(&g_gmax_u, mu);
    }
}

// ---------------- 3b) scatter + w ----------------
__global__ void scatter_kernel() {
    const int i = blockIdx.x * 256 + threadIdx.x;
    const int r = g_rank[i];
    const float gi = g_g[i];
    const float gmax = mono2f(g_gmax_u);
    g_gs[r] = gi;
    g_gidx[r] = i;
    g_w[r] = expf(gi - gmax);
}

// ---------------- 4) scan phase 1 ----------------
__global__ void scan1_kernel() {
    __shared__ int   sidx[CHUNK];
    __shared__ float sw[CHUNK];
    const int blk = blockIdx.x;
    const int c = threadIdx.x;
    const int base = blk * CHUNK;
    if (c < CHUNK) { sidx[c] = g_gidx[base + c]; sw[c] = g_w[base + c]; }
    __syncthreads();
    float sH = 0.f, sE = 0.f, sW = 0.f;
    #pragma unroll
    for (int r = 0; r < CHUNK; r++) {
        float v = g_h[(size_t)sidx[r] * F_DIM + c];
        float w = sw[r];
        sH += v; sE += w * v; sW += w;
    }
    g_pH[blk * F_DIM + c] = sH;
    g_pE[blk * F_DIM + c] = sE;
    if (c == 0) g_pW[blk] = sW;
}

// ---------------- 5) scan phase 2 ----------------
__global__ void scan2_kernel() {   // grid 32 x 256 threads
    const unsigned FULL = 0xffffffffu;
    const int warp = threadIdx.x >> 5, lane = threadIdx.x & 31;
    const int c = blockIdx.x * 8 + warp;
    float carry = 0.f;
    for (int s = 0; s < NCHUNK; s += 32) {
        float v = g_pH[(s + lane) * F_DIM + c];
        float x = v;
        #pragma unroll
        for (int o = 1; o < 32; o <<= 1) {
            float t = __shfl_up_sync(FULL, x, o);
            if (lane >= o) x += t;
        }
        g_chOffH[(s + lane) * F_DIM + c] = carry + x - v;
        carry += __shfl_sync(FULL, x, 31);
    }
    g_prefH[(size_t)N_ROWS * F_DIM + c] = carry;
    float carryE = 0.f;
    for (int s = NCHUNK - 32; s >= 0; s -= 32) {
        float v = g_pE[(s + lane) * F_DIM + c];
        float x = v;
        #pragma unroll
        for (int o = 1; o < 32; o <<= 1) {
            float t = __shfl_down_sync(FULL, x, o);
            if (lane + o < 32) x += t;
        }
        g_chOffE[(s + lane) * F_DIM + c] = carryE + x - v;
        carryE += __shfl_sync(FULL, x, 0);
    }
    g_sufE[(size_t)N_ROWS * F_DIM + c] = 0.f;
    if (blockIdx.x == 0 && warp == 0) {
        float cw = 0.f;
        for (int s = NCHUNK - 32; s >= 0; s -= 32) {
            float v = g_pW[s + lane];
            float x = v;
            #pragma unroll
            for (int o = 1; o < 32; o <<= 1) {
                float t = __shfl_down_sync(FULL, x, o);
                if (lane + o < 32) x += t;
            }
            g_chOffW[s + lane] = cw + x - v;
            cw += __shfl_sync(FULL, x, 0);
        }
        if (lane == 0) g_sufW[N_ROWS] = 0.f;
    }
}

// ---------------- 6) scan phase 3 ----------------
__global__ void scan3_kernel() {
    __shared__ int   sidx[CHUNK];
    __shared__ float sw[CHUNK];
    const int blk = blockIdx.x;
    const int c = threadIdx.x;
    const int base = blk * CHUNK;
    if (c < CHUNK) { sidx[c] = g_gidx[base + c]; sw[c] = g_w[base + c]; }
    __syncthreads();
    float run = g_chOffH[blk * F_DIM + c];
    #pragma unroll
    for (int r = 0; r < CHUNK; r++) {
        int k = base + r;
        g_prefH[(size_t)k * F_DIM + c] = run;
        run += g_h[(size_t)sidx[r] * F_DIM + c];
    }
    float runE = g_chOffE[blk * F_DIM + c];
    float runW = g_chOffW[blk];
    #pragma unroll
    for (int r = CHUNK - 1; r >= 0; r--) {
        int k = base + r;
        runE += sw[r] * g_h[(size_t)sidx[r] * F_DIM + c];
        g_sufE[(size_t)k * F_DIM + c] = runE;
        runW += sw[r];
        if (c == 0) g_sufW[k] = runW;
    }
}

// ---------------- 7) output ----------------
__global__ void out_kernel(float* __restrict__ out) {
    const int warp = threadIdx.x >> 5, lane = threadIdx.x & 31;
    const int i = blockIdx.x * 8 + warp;
    int k; float alpha, beta, inv;
    if (lane == 0) {
        float fi = g_f[i];
        float gmax = g_gs[N_ROWS - 1];
        float t = fi + gmax;
        float thr = -fi;
        int lo = 0, hi = N_ROWS;
        while (lo < hi) {
            int mid = (lo + hi) >> 1;
            if (g_gs[mid] <= thr) lo = mid + 1; else hi = mid;
        }
        k = lo;
        alpha = expf(fminf(t, 0.f));
        beta  = expf(-fmaxf(t, 0.f));
        inv = 1.f / (alpha * g_sufW[k] + beta * (float)k);
    }
    k     = __shfl_sync(0xffffffffu, k, 0);
    alpha = __shfl_sync(0xffffffffu, alpha, 0);
    beta  = __shfl_sync(0xffffffffu, beta, 0);
    inv   = __shfl_sync(0xffffffffu, inv, 0);
    const float4* pe = (const float4*)(g_sufE  + (size_t)k * F_DIM);
    const float4* ph = (const float4*)(g_prefH + (size_t)k * F_DIM);
    float4* po = (float4*)(out + (size_t)i * F_DIM);
    #pragma unroll
    for (int j = 0; j < 2; j++) {
        int idx = lane + 32 * j;
        float4 e = pe[idx], h = ph[idx];
        float4 y;
        y.x = (alpha * e.x + beta * h.x) * inv;
        y.y = (alpha * e.y + beta * h.y) * inv;
        y.z = (alpha * e.z + beta * h.z) * inv;
        y.w = (alpha * e.w + beta * h.w) * inv;
        y.x = (y.x > 0.f) ? y.x : expm1f(y.x);
        y.y = (y.y > 0.f) ? y.y : expm1f(y.y);
        y.z = (y.z > 0.f) ? y.z : expm1f(y.z);
        y.w = (y.w > 0.f) ? y.w : expm1f(y.w);
        po[idx] = y;
    }
}

// ---------------- launch ----------------
extern "C" void kernel_launch(void* const* d_in, const int* in_sizes, int n_in,
                              void* d_out, int out_size) {
    const float* x = (const float*)d_in[0];
    const float* W = (const float*)d_in[1];
    const float* a = (const float*)d_in[2];
    float* out = (float*)d_out;

    convert_kernel<<<XBLOCKS + WBLOCKS, 256>>>(x, W);

    cudaFuncSetAttribute(gemm_mma_kernel,
                         cudaFuncAttributeMaxDynamicSharedMemorySize, 2 * BUFSZ + 2048);
    gemm_mma_kernel<<<dim3(F_DIM / 128, N_ROWS / 128), 256, 2 * BUFSZ + 2048>>>(a);

    rank_kernel<<<dim3(N_ROWS / 256, 8), 256>>>();
    scatter_kernel<<<N_ROWS / 256, 256>>>();
    scan1_kernel<<<NCHUNK, F_DIM>>>();
    scan2_kernel<<<32, 256>>>();
    scan3_kernel<<<NCHUNK, F_DIM>>>();
    out_kernel<<<N_ROWS / 8, 256>>>(out);
}

// round 7
// speedup vs baseline: 3.1667x; 1.0469x over previous
#include <cuda_runtime.h>
#include <cuda_bf16.h>
#include <math.h>
#include <cstdint>

#define N_ROWS 8192
#define K_DIM  512
#define F_DIM  256
#define NCHUNK 512
#define CHUNK  16

// ---------------- scratch (device globals) ----------------
__device__ __nv_bfloat16 g_xh[N_ROWS * K_DIM];
__device__ __nv_bfloat16 g_xl[N_ROWS * K_DIM];
__device__ __nv_bfloat16 g_wth[F_DIM * K_DIM];   // W^T hi  [256][512]
__device__ __nv_bfloat16 g_wtl[F_DIM * K_DIM];   // W^T lo
__device__ float g_h[N_ROWS * F_DIM];
__device__ float g_f[N_ROWS];
__device__ float g_g[N_ROWS];
__device__ float g_gs[N_ROWS];
__device__ int   g_gidx[N_ROWS];
__device__ int   g_rank[N_ROWS];
__device__ int   g_cnt[N_ROWS];
// local scans: row k = [locH prefix (256) | locE suffix (256)]
__device__ float g_loc[(size_t)(N_ROWS + 1) * 512];
// chunk offsets: row b = [choffH (256) | choffE (256)]
__device__ float g_choff[(size_t)(NCHUNK + 1) * 512];
__device__ float g_aggH[NCHUNK * F_DIM];
__device__ float g_aggE[NCHUNK * F_DIM];
__device__ float g_aggW[NCHUNK];
__device__ float g_lsufW[N_ROWS + 1];
__device__ float g_choffW[NCHUNK + 1];

// ---------------- helpers ----------------
__device__ __forceinline__ uint32_t smem_u32(const void* p) {
    uint32_t a;
    asm("{ .reg .u64 t; cvta.to.shared.u64 t, %1; cvt.u32.u64 %0, t; }" : "=r"(a) : "l"(p));
    return a;
}
__device__ __forceinline__ void ldsm_x4(uint32_t (&r)[4], uint32_t addr) {
    asm volatile("ldmatrix.sync.aligned.m8n8.x4.shared.b16 {%0,%1,%2,%3}, [%4];"
                 : "=r"(r[0]), "=r"(r[1]), "=r"(r[2]), "=r"(r[3]) : "r"(addr));
}
__device__ __forceinline__ void mma16816(float (&d)[4], const uint32_t (&a)[4],
                                         uint32_t b0, uint32_t b1) {
    asm volatile(
        "mma.sync.aligned.m16n8k16.row.col.f32.bf16.bf16.f32 "
        "{%0,%1,%2,%3}, {%4,%5,%6,%7}, {%8,%9}, {%0,%1,%2,%3};"
        : "+f"(d[0]), "+f"(d[1]), "+f"(d[2]), "+f"(d[3])
        : "r"(a[0]), "r"(a[1]), "r"(a[2]), "r"(a[3]), "r"(b0), "r"(b1));
}
__device__ __forceinline__ void cp16(uint32_t dst, const void* src) {
    asm volatile("cp.async.cg.shared.global [%0], [%1], 16;" :: "r"(dst), "l"(src));
}

// ---------------- 0) fused convert: x -> (xh,xl), W -> (Wth,Wtl), zero-inits ----
#define XBLOCKS (N_ROWS * K_DIM / 1024)   // 4096
#define WBLOCKS (K_DIM * F_DIM / 256)     // 512
__global__ void convert_kernel(const float* __restrict__ x, const float* __restrict__ W) {
    if (blockIdx.x < XBLOCKS) {
        const int idx = (blockIdx.x * 256 + threadIdx.x) * 4;
        float4 v = *(const float4*)(x + idx);
        __nv_bfloat16 h0 = __float2bfloat16_rn(v.x), h1 = __float2bfloat16_rn(v.y);
        __nv_bfloat16 h2 = __float2bfloat16_rn(v.z), h3 = __float2bfloat16_rn(v.w);
        __nv_bfloat16 l0 = __float2bfloat16_rn(v.x - __bfloat162float(h0));
        __nv_bfloat16 l1 = __float2bfloat16_rn(v.y - __bfloat162float(h1));
        __nv_bfloat16 l2 = __float2bfloat16_rn(v.z - __bfloat162float(h2));
        __nv_bfloat16 l3 = __float2bfloat16_rn(v.w - __bfloat162float(h3));
        __nv_bfloat162* ph = (__nv_bfloat162*)(g_xh + idx);
        __nv_bfloat162* pl = (__nv_bfloat162*)(g_xl + idx);
        ph[0] = __nv_bfloat162(h0, h1); ph[1] = __nv_bfloat162(h2, h3);
        pl[0] = __nv_bfloat162(l0, l1); pl[1] = __nv_bfloat162(l2, l3);
    } else {
        const int idx = (blockIdx.x - XBLOCKS) * 256 + threadIdx.x;  // 0..131071
        if (idx < N_ROWS) {
            g_rank[idx] = 0; g_cnt[idx] = 0;
            g_f[idx] = 0.f;  g_g[idx] = 0.f;
        }
        const int k = idx >> 8;
        const int n = idx & 255;
        float v = W[idx];
        __nv_bfloat16 h = __float2bfloat16_rn(v);
        __nv_bfloat16 l = __float2bfloat16_rn(v - __bfloat162float(h));
        g_wth[(size_t)n * K_DIM + k] = h;
        g_wtl[(size_t)n * K_DIM + k] = l;
    }
}

// ---------------- 1) mma.sync GEMM: h = x @ W (+ fused f/g partials) ----------------
#define GSTRIDE 72
#define TILE_B  18432
#define BUFSZ   73728
#define SM_A1A2 (2 * BUFSZ)

__device__ __forceinline__ void load_chunk_async(uint32_t sb, int buf, int k0,
                                                 int bm, int bn, int tid) {
    uint32_t base = sb + buf * BUFSZ;
    #pragma unroll
    for (int l = 0; l < 4; l++) {
        int idx = tid + l * 256;
        int r = idx >> 3, c8 = (idx & 7) * 8;
        uint32_t off = (uint32_t)(r * GSTRIDE + c8) * 2;
        cp16(base + off,              g_xh  + (size_t)(bm + r) * K_DIM + k0 + c8);
        cp16(base + TILE_B + off,     g_xl  + (size_t)(bm + r) * K_DIM + k0 + c8);
        cp16(base + 2 * TILE_B + off, g_wth + (size_t)(bn + r) * K_DIM + k0 + c8);
        cp16(base + 3 * TILE_B + off, g_wtl + (size_t)(bn + r) * K_DIM + k0 + c8);
    }
}

__global__ void __launch_bounds__(256, 1) gemm_mma_kernel(const float* __restrict__ a) {
    extern __shared__ char smem[];
    const uint32_t sb = smem_u32(smem);
    float* sa = (float*)(smem + SM_A1A2);
    const int tid = threadIdx.x;
    const int wid = tid >> 5, lane = tid & 31;
    const int warp_m = wid >> 2;
    const int warp_n = wid & 3;
    const int bm = blockIdx.y * 128;
    const int bn = blockIdx.x * 128;

    float acc[4][4][4];
    #pragma unroll
    for (int mt = 0; mt < 4; mt++)
        #pragma unroll
        for (int nt = 0; nt < 4; nt++)
            #pragma unroll
            for (int r = 0; r < 4; r++) acc[mt][nt][r] = 0.f;

    const int a_row = warp_m * 64 + (lane & 15);
    const int a_col = (lane >> 4) * 8;
    const int b_row = warp_n * 32 + ((lane >> 4) & 1) * 8 + (lane & 7);
    const int b_col = ((lane >> 3) & 1) * 8;

    sa[tid] = a[tid];
    sa[256 + tid] = a[256 + tid];
    load_chunk_async(sb, 0, 0, bm, bn, tid);
    asm volatile("cp.async.commit_group;" ::: "memory");

    for (int i = 0; i < 8; i++) {
        asm volatile("cp.async.wait_group 0;" ::: "memory");
        __syncthreads();
        if (i < 7) {
            load_chunk_async(sb, (i & 1) ^ 1, (i + 1) * 64, bm, bn, tid);
            asm volatile("cp.async.commit_group;" ::: "memory");
        }
        const uint32_t bufb = sb + (i & 1) * BUFSZ;
        #pragma unroll
        for (int kk = 0; kk < 4; kk++) {
            uint32_t ah[4][4], al[4][4], bh[2][4], bl[2][4];
            #pragma unroll
            for (int mt = 0; mt < 4; mt++) {
                uint32_t off = (uint32_t)((a_row + mt * 16) * GSTRIDE + kk * 16 + a_col) * 2;
                ldsm_x4(ah[mt], bufb + off);
                ldsm_x4(al[mt], bufb + TILE_B + off);
            }
            #pragma unroll
            for (int np = 0; np < 2; np++) {
                uint32_t off = (uint32_t)((b_row + np * 16) * GSTRIDE + kk * 16 + b_col) * 2;
                ldsm_x4(bh[np], bufb + 2 * TILE_B + off);
                ldsm_x4(bl[np], bufb + 3 * TILE_B + off);
            }
            #pragma unroll
            for (int mt = 0; mt < 4; mt++) {
                #pragma unroll
                for (int nt = 0; nt < 4; nt++) {
                    int np = nt >> 1, p = (nt & 1) * 2;
                    mma16816(acc[mt][nt], ah[mt], bh[np][p], bh[np][p + 1]);
                    mma16816(acc[mt][nt], ah[mt], bl[np][p], bl[np][p + 1]);
                    mma16816(acc[mt][nt], al[mt], bh[np][p], bh[np][p + 1]);
                }
            }
        }
        __syncthreads();
    }

    // epilogue: write h + fused f/g partial dot products
    const int g = lane >> 2, t = lane & 3;
    #pragma unroll
    for (int mt = 0; mt < 4; mt++) {
        const int row = bm + warp_m * 64 + mt * 16 + g;
        float f0 = 0.f, g0 = 0.f, f1 = 0.f, g1 = 0.f;
        #pragma unroll
        for (int nt = 0; nt < 4; nt++) {
            const int colS = bn + warp_n * 32 + nt * 8 + t * 2;  // global col in [0,256)
            const float a1c0 = sa[colS],       a1c1 = sa[colS + 1];
            const float a2c0 = sa[256 + colS], a2c1 = sa[256 + colS + 1];
            *(float2*)(g_h + (size_t)row * F_DIM + colS) =
                make_float2(acc[mt][nt][0], acc[mt][nt][1]);
            *(float2*)(g_h + (size_t)(row + 8) * F_DIM + colS) =
                make_float2(acc[mt][nt][2], acc[mt][nt][3]);
            f0 += acc[mt][nt][0] * a1c0 + acc[mt][nt][1] * a1c1;
            g0 += acc[mt][nt][0] * a2c0 + acc[mt][nt][1] * a2c1;
            f1 += acc[mt][nt][2] * a1c0 + acc[mt][nt][3] * a1c1;
            g1 += acc[mt][nt][2] * a2c0 + acc[mt][nt][3] * a2c1;
        }
        #pragma unroll
        for (int o = 1; o < 4; o <<= 1) {
            f0 += __shfl_xor_sync(0xffffffffu, f0, o);
            g0 += __shfl_xor_sync(0xffffffffu, g0, o);
            f1 += __shfl_xor_sync(0xffffffffu, f1, o);
            g1 += __shfl_xor_sync(0xffffffffu, g1, o);
        }
        if (t == 0) {
            atomicAdd(g_f + row, f0);
            atomicAdd(g_g + row, g0);
            atomicAdd(g_f + row + 8, f1);
            atomicAdd(g_g + row + 8, g1);
        }
    }
}

// ---------------- 2) rank-sort + inline scatter (last contributor wins) ----------
__global__ void rank_kernel() {
    __shared__ float sj[1024];
    const int tid = threadIdx.x;
    const int bi = blockIdx.x;          // 32
    const int bj = blockIdx.y;          // 8
    const int jbase = bj * 1024;
    *(float4*)&sj[tid * 4] = *(const float4*)(g_g + jbase + tid * 4);
    __syncthreads();
    const int i = bi * 256 + tid;
    const float vi = g_g[i];
    int cnt = 0;
    #pragma unroll 4
    for (int jj = 0; jj < 1024; jj += 4) {
        float4 v = *(const float4*)&sj[jj];
        int j0 = jbase + jj;
        cnt += (v.x < vi) || (v.x == vi && (j0 + 0) < i);
        cnt += (v.y < vi) || (v.y == vi && (j0 + 1) < i);
        cnt += (v.z < vi) || (v.z == vi && (j0 + 2) < i);
        cnt += (v.w < vi) || (v.w == vi && (j0 + 3) < i);
    }
    atomicAdd(&g_rank[i], cnt);
    __threadfence();
    if (atomicAdd(&g_cnt[i], 1) == 7) {   // 8th (last) contributor scatters
        int r = atomicAdd(&g_rank[i], 0); // coherent read of final rank
        g_gs[r] = vi;
        g_gidx[r] = i;
    }
}

// ---------------- 3) scan A: local prefix/suffix per chunk + aggregates ----------
__global__ void scanA_kernel() {          // grid NCHUNK(512) x 256
    __shared__ int   sidx[CHUNK];
    __shared__ float sw[CHUNK];
    const int blk = blockIdx.x;
    const int c = threadIdx.x;
    const int base = blk * CHUNK;
    if (c < CHUNK) {
        sidx[c] = g_gidx[base + c];
        sw[c] = expf(g_gs[base + c] - g_gs[N_ROWS - 1]);
    }
    __syncthreads();
    float hv[CHUNK];
    #pragma unroll
    for (int r = 0; r < CHUNK; r++)
        hv[r] = g_h[(size_t)sidx[r] * F_DIM + c];
    float run = 0.f;
    #pragma unroll
    for (int r = 0; r < CHUNK; r++) {
        g_loc[(size_t)(base + r) * 512 + c] = run;       // exclusive prefix of H
        run += hv[r];
    }
    g_aggH[blk * F_DIM + c] = run;
    float runE = 0.f;
    #pragma unroll
    for (int r = CHUNK - 1; r >= 0; r--) {
        runE += sw[r] * hv[r];
        g_loc[(size_t)(base + r) * 512 + 256 + c] = runE; // inclusive suffix of w*H
    }
    g_aggE[blk * F_DIM + c] = runE;
    if (c == 0) {
        float runW = 0.f;
        #pragma unroll
        for (int r = CHUNK - 1; r >= 0; r--) {
            runW += sw[r];
            g_lsufW[base + r] = runW;
        }
        g_aggW[blk] = runW;
    }
}

// ---------------- 4) scan B: cross-chunk offsets ----------------
__global__ void scanB_kernel() {          // grid 32 x 256
    const unsigned FULL = 0xffffffffu;
    const int warp = threadIdx.x >> 5, lane = threadIdx.x & 31;
    const int c = blockIdx.x * 8 + warp;  // 0..255
    float carry = 0.f;
    for (int s = 0; s < NCHUNK; s += 32) {
        float v = g_aggH[(s + lane) * F_DIM + c];
        float x = v;
        #pragma unroll
        for (int o = 1; o < 32; o <<= 1) {
            float t = __shfl_up_sync(FULL, x, o);
            if (lane >= o) x += t;
        }
        g_choff[(size_t)(s + lane) * 512 + c] = carry + x - v;   // exclusive prefix
        carry += __shfl_sync(FULL, x, 31);
    }
    float carryE = 0.f;
    for (int s = NCHUNK - 32; s >= 0; s -= 32) {
        float v = g_aggE[(s + lane) * F_DIM + c];
        float x = v;
        #pragma unroll
        for (int o = 1; o < 32; o <<= 1) {
            float t = __shfl_down_sync(FULL, x, o);
            if (lane + o < 32) x += t;
        }
        g_choff[(size_t)(s + lane) * 512 + 256 + c] = carryE + x - v;  // exclusive suffix
        carryE += __shfl_sync(FULL, x, 0);
    }
    if (lane == 0) {
        g_choff[(size_t)NCHUNK * 512 + c] = carry;       // total H (k == 8192 case)
        g_choff[(size_t)NCHUNK * 512 + 256 + c] = 0.f;
        g_loc[(size_t)N_ROWS * 512 + c] = 0.f;           // loc row 8192 = zeros
        g_loc[(size_t)N_ROWS * 512 + 256 + c] = 0.f;
    }
    if (blockIdx.x == 0 && warp == 0) {
        float cw = 0.f;
        for (int s = NCHUNK - 32; s >= 0; s -= 32) {
            float v = g_aggW[s + lane];
            float x = v;
            #pragma unroll
            for (int o = 1; o < 32; o <<= 1) {
                float t = __shfl_down_sync(FULL, x, o);
                if (lane + o < 32) x += t;
            }
            g_choffW[s + lane] = cw + x - v;
            cw += __shfl_sync(FULL, x, 0);
        }
        if (lane == 0) { g_choffW[NCHUNK] = 0.f; g_lsufW[N_ROWS] = 0.f; }
    }
}

// ---------------- 5) output: binary search + compose + elu ----------------
__global__ void out_kernel(float* __restrict__ out) {
    const int warp = threadIdx.x >> 5, lane = threadIdx.x & 31;
    const int i = blockIdx.x * 8 + warp;
    int k; float alpha, beta, inv;
    if (lane == 0) {
        float fi = g_f[i];
        float gmax = g_gs[N_ROWS - 1];
        float t = fi + gmax;
        float thr = -fi;
        int lo = 0, hi = N_ROWS;
        while (lo < hi) {
            int mid = (lo + hi) >> 1;
            if (g_gs[mid] <= thr) lo = mid + 1; else hi = mid;
        }
        k = lo;
        alpha = expf(fminf(t, 0.f));
        beta  = expf(-fmaxf(t, 0.f));
        float sufWk = g_choffW[k >> 4] + g_lsufW[k];
        inv = 1.f / (alpha * sufWk + beta * (float)k);
    }
    k     = __shfl_sync(0xffffffffu, k, 0);
    alpha = __shfl_sync(0xffffffffu, alpha, 0);
    beta  = __shfl_sync(0xffffffffu, beta, 0);
    inv   = __shfl_sync(0xffffffffu, inv, 0);
    const float* loc = g_loc   + (size_t)k * 512;
    const float* cof = g_choff + (size_t)(k >> 4) * 512;
    float4* po = (float4*)(out + (size_t)i * F_DIM);
    #pragma unroll
    for (int j = 0; j < 2; j++) {
        int idx = lane + 32 * j;
        float4 lh = ((const float4*)loc)[idx];
        float4 le = ((const float4*)(loc + 256))[idx];
        float4 ch = ((const float4*)cof)[idx];
        float4 ce = ((const float4*)(cof + 256))[idx];
        float4 y;
        y.x = (alpha * (ce.x + le.x) + beta * (ch.x + lh.x)) * inv;
        y.y = (alpha * (ce.y + le.y) + beta * (ch.y + lh.y)) * inv;
        y.z = (alpha * (ce.z + le.z) + beta * (ch.z + lh.z)) * inv;
        y.w = (alpha * (ce.w + le.w) + beta * (ch.w + lh.w)) * inv;
        y.x = (y.x > 0.f) ? y.x : expm1f(y.x);
        y.y = (y.y > 0.f) ? y.y : expm1f(y.y);
        y.z = (y.z > 0.f) ? y.z : expm1f(y.z);
        y.w = (y.w > 0.f) ? y.w : expm1f(y.w);
        po[idx] = y;
    }
}

// ---------------- launch ----------------
extern "C" void kernel_launch(void* const* d_in, const int* in_sizes, int n_in,
                              void* d_out, int out_size) {
    const float* x = (const float*)d_in[0];
    const float* W = (const float*)d_in[1];
    const float* a = (const float*)d_in[2];
    float* out = (float*)d_out;

    convert_kernel<<<XBLOCKS + WBLOCKS, 256>>>(x, W);

    cudaFuncSetAttribute(gemm_mma_kernel,
                         cudaFuncAttributeMaxDynamicSharedMemorySize, 2 * BUFSZ + 2048);
    gemm_mma_kernel<<<dim3(F_DIM / 128, N_ROWS / 128), 256, 2 * BUFSZ + 2048>>>(a);

    rank_kernel<<<dim3(N_ROWS / 256, 8), 256>>>();
    scanA_kernel<<<NCHUNK, F_DIM>>>();
    scanB_kernel<<<32, 256>>>();
    out_kernel<<<N_ROWS / 8, 256>>>(out);
}